// round 16
// baseline (speedup 1.0000x reference)
#include <cuda_runtime.h>
#include <cuda_bf16.h>
#include <cuda_fp16.h>
#include <stdint.h>
#include <math.h>

// Problem constants
#define TT 2048      // tokens (B*S)
#define HH 768       // hidden
#define II 1536      // intermediate
#define EE 8         // experts
#define KK 2         // top-k
#define CAP 768      // capacity
#define SLOTS (KK*CAP)   // 1536 slot rows per expert

// ---------------- scratch (device globals; allocation-free) ----------------
__device__ float g_probs[TT * EE];                // full softmax probs (64KB)
__device__ int   g_topk_idx[TT * KK];
__device__ float g_topk_w[TT * KK];
__device__ int   g_slot[TT * KK];
__device__ int   g_list[EE * SLOTS];
__device__ float g_wslot[EE * SLOTS];             // combine weight per (e,slot)
__device__ int   g_cnt[KK * EE];
__device__ int   g_drop[KK * EE];
__device__ __half g_xh[TT * HH];                  // x as fp16 (3MB)
__device__ __half g_w1h[EE * HH * II];            // w1 fp16 (~19MB)
__device__ __half g_w3h[EE * HH * II];            // w3 fp16 (~19MB)
__device__ __half g_w2h[EE * II * HH];            // w2 fp16 (~19MB)
__device__ __half g_hbufh[EE * SLOTS * II];       // SwiGLU intermediate fp16 (~38MB)

// ---------------- PTX helpers ----------------
__device__ __forceinline__ uint32_t s2u(const void* p) {
    uint32_t a;
    asm("{ .reg .u64 t; cvta.to.shared.u64 t, %1; cvt.u32.u64 %0, t; }" : "=r"(a) : "l"(p));
    return a;
}
__device__ __forceinline__ void cpa16(uint32_t dst, const void* src) {
    asm volatile("cp.async.cg.shared.global [%0], [%1], 16;" :: "r"(dst), "l"(src));
}
__device__ __forceinline__ void cpa_commit() { asm volatile("cp.async.commit_group;" ::: "memory"); }
template<int N> __device__ __forceinline__ void cpa_wait() {
    asm volatile("cp.async.wait_group %0;" :: "n"(N) : "memory");
}
__device__ __forceinline__ void ldsm4(uint32_t* r, uint32_t addr) {
    asm volatile("ldmatrix.sync.aligned.m8n8.x4.shared.b16 {%0,%1,%2,%3}, [%4];"
        : "=r"(r[0]), "=r"(r[1]), "=r"(r[2]), "=r"(r[3]) : "r"(addr));
}
__device__ __forceinline__ void ldsm4t(uint32_t* r, uint32_t addr) {
    asm volatile("ldmatrix.sync.aligned.m8n8.x4.trans.shared.b16 {%0,%1,%2,%3}, [%4];"
        : "=r"(r[0]), "=r"(r[1]), "=r"(r[2]), "=r"(r[3]) : "r"(addr));
}
__device__ __forceinline__ void mma16(float* d, const uint32_t* a, const uint32_t* b) {
    asm volatile(
        "mma.sync.aligned.m16n8k16.row.col.f32.f16.f16.f32 "
        "{%0,%1,%2,%3}, {%4,%5,%6,%7}, {%8,%9}, {%0,%1,%2,%3};"
        : "+f"(d[0]), "+f"(d[1]), "+f"(d[2]), "+f"(d[3])
        : "r"(a[0]), "r"(a[1]), "r"(a[2]), "r"(a[3]), "r"(b[0]), "r"(b[1]));
}

// ---------------- fp16 pre-convert: 8 floats/thread, uint4 store ----------
__global__ void cvth3_kernel(const float4* __restrict__ w1,
                             const float4* __restrict__ w3,
                             const float4* __restrict__ w2,
                             uint4* __restrict__ d1,
                             uint4* __restrict__ d3,
                             uint4* __restrict__ d2, int n8) {
    int i = blockIdx.x * blockDim.x + threadIdx.x;
    if (i >= n8) return;
    const float4* src = (blockIdx.y == 0) ? w1 : (blockIdx.y == 1) ? w3 : w2;
    uint4* dst = (blockIdx.y == 0) ? d1 : (blockIdx.y == 1) ? d3 : d2;
    float4 v0 = src[2 * i];
    float4 v1 = src[2 * i + 1];
    __half2 h0 = __floats2half2_rn(v0.x, v0.y);
    __half2 h1 = __floats2half2_rn(v0.z, v0.w);
    __half2 h2 = __floats2half2_rn(v1.x, v1.y);
    __half2 h3 = __floats2half2_rn(v1.z, v1.w);
    uint4 o;
    o.x = *(uint32_t*)&h0; o.y = *(uint32_t*)&h1;
    o.z = *(uint32_t*)&h2; o.w = *(uint32_t*)&h3;
    dst[i] = o;
}

// ---------------- zero out (float4) ----------------
__global__ void zero_out_kernel(float4* __restrict__ out4, int n4, float* out, int n) {
    int i = blockIdx.x * blockDim.x + threadIdx.x;
    if (i < n4) out4[i] = make_float4(0.f, 0.f, 0.f, 0.f);
    if (i == 0) for (int j = n4 * 4; j < n; j++) out[j] = 0.0f;
}

// ---------------- routing: warp-per-token, wg staged in SMEM ---------------
__global__ void __launch_bounds__(512) routing_kernel(const float* __restrict__ x,
                                                      const float* __restrict__ wg) {
    __shared__ float swgT[EE][HH + 8];
    int tid = threadIdx.x;
    for (int i = tid; i < HH * EE; i += 512) {
        int j = i >> 3, e = i & 7;
        swgT[e][j] = wg[i];
    }
    __syncthreads();

    int lane = tid & 31, w = tid >> 5;
    int t = blockIdx.x * 16 + w;
    const float* xr = x + (size_t)t * HH;
    float acc[EE] = {};
#pragma unroll
    for (int i = 0; i < HH / 128; i++) {            // 6 iterations
        int j = i * 128 + lane * 4;
        float4 xv = *(const float4*)(xr + j);
        __half2 hx0 = __floats2half2_rn(xv.x, xv.y);
        __half2 hx1 = __floats2half2_rn(xv.z, xv.w);
        *(__half2*)&g_xh[(size_t)t * HH + j]     = hx0;
        *(__half2*)&g_xh[(size_t)t * HH + j + 2] = hx1;
#pragma unroll
        for (int e = 0; e < EE; e++) {
            float4 wv = *(const float4*)&swgT[e][j];
            acc[e] += xv.x * wv.x + xv.y * wv.y + xv.z * wv.z + xv.w * wv.w;
        }
    }
#pragma unroll
    for (int o = 16; o; o >>= 1)
#pragma unroll
        for (int e = 0; e < EE; e++) acc[e] += __shfl_xor_sync(0xffffffffu, acc[e], o);

    if (lane == 0) {
        float mx = acc[0];
        for (int e = 1; e < EE; e++) mx = fmaxf(mx, acc[e]);
        float p[EE], s = 0.0f;
        for (int e = 0; e < EE; e++) { p[e] = expf(acc[e] - mx); s += p[e]; }
        for (int e = 0; e < EE; e++) p[e] /= s;
        for (int e = 0; e < EE; e++) g_probs[t * EE + e] = p[e];
        int e0 = 0;
        for (int e = 1; e < EE; e++) if (p[e] > p[e0]) e0 = e;
        int e1 = -1;
        for (int e = 0; e < EE; e++) {
            if (e == e0) continue;
            if (e1 < 0 || p[e] > p[e1]) e1 = e;
        }
        float ps = p[e0] + p[e1] + 1e-8f;
        float w0 = fminf(fmaxf(p[e0] / ps, 1e-8f), 10.0f);
        float w1 = fminf(fmaxf(p[e1] / ps, 1e-8f), 10.0f);
        g_topk_idx[t * 2 + 0] = e0;
        g_topk_idx[t * 2 + 1] = e1;
        g_topk_w[t * 2 + 0] = w0;
        g_topk_w[t * 2 + 1] = w1;
    }
}

// ---------------- scan: one warp per (k,e), zero barriers -------------------
// ranks are independent per (k,e) pair (cumsum over tokens within each pair).
__global__ void scan_kernel() {       // 1 block, 512 threads = 16 warps
    int w = threadIdx.x >> 5, lane = threadIdx.x & 31;
    int k = w >> 3, e = w & 7;
    int cnt = 0;
    for (int t0 = 0; t0 < TT; t0 += 32) {
        int t = t0 + lane;
        bool m = (g_topk_idx[t * 2 + k] == e);
        unsigned mask = __ballot_sync(0xffffffffu, m);
        if (m) {
            int rank = cnt + __popc(mask & ((1u << lane) - 1)) + 1;
            bool kept = (rank <= CAP);
            int slot = kept ? (k * CAP + rank - 1) : -1;
            g_slot[t * 2 + k] = slot;
            if (kept) {
                g_list[e * SLOTS + slot] = t;
                g_wslot[e * SLOTS + slot] = g_topk_w[t * 2 + k];
            }
        }
        cnt += __popc(mask);
    }
    if (lane == 0) {
        int c = min(cnt, CAP);
        g_cnt[k * EE + e] = c;
        g_drop[k * EE + e] = cnt - c;
    }
}

// ================ GEMM1: fp16 mma + ldmatrix, KC=64, 3-stage, 2 CTAs/SM ====
// CTA: M=128 slots x N=128 (64 w1-cols + 64 w3-cols). 256 threads, 8 warps.
#define KC 64                   // K elements per chunk
#define APITCH 72               // halves per A row (64 data + 8 pad) = 144B
#define BPITCH 136              // halves per B k-row (128 data + 8 pad) = 272B
#define ABUF (128*APITCH)       // halves
#define BBUF (KC*BPITCH)        // halves
#define G1_SMEM ((3*ABUF + 3*BBUF) * 2 + 512)
__global__ void __launch_bounds__(256, 2) gemm1_mma() {
    extern __shared__ __half sh[];
    __half* Ash = sh;                 // 3 x ABUF
    __half* Bsh = sh + 3 * ABUF;      // 3 x BBUF
    int* stok = (int*)(Bsh + 3 * BBUF);

    int e = blockIdx.z, by = blockIdx.y, bx = blockIdx.x; // bx 0..23
    int kslot = (by >= 6) ? 1 : 0;
    int cnt = g_cnt[kslot * EE + e];
    int tile0 = (by - kslot * 6) * 128;
    if (tile0 >= cnt) return;
    int valid = min(128, cnt - tile0);
    int slot0 = by * 128;
    int tid = threadIdx.x;
    int lane = tid & 31, w = tid >> 5;
    int warpM = w >> 2, warpN = w & 3;

    if (tid < 128)
        stok[tid] = (tid < valid) ? g_list[e * SLOTS + slot0 + tid]
                                  : g_list[e * SLOTS + slot0];
    __syncthreads();

    const __half* w1b = g_w1h + (size_t)e * HH * II + bx * 64;
    const __half* w3b = g_w3h + (size_t)e * HH * II + bx * 64;

    auto fill = [&](int buf, int c) {
        uint32_t au = s2u(Ash + buf * ABUF);
        uint32_t bu_ = s2u(Bsh + buf * BBUF);
        int k0 = c * KC;
#pragma unroll
        for (int i = tid; i < 1024; i += 256) {   // A: 128 rows x 64 halves
            int row = i >> 3, seg = i & 7;
            cpa16(au + (uint32_t)(row * APITCH + seg * 8) * 2,
                  g_xh + (size_t)stok[row] * HH + k0 + seg * 8);
        }
#pragma unroll
        for (int i = tid; i < 1024; i += 256) {   // B: 64 k-rows x (64 G + 64 U)
            int k = i >> 4, seg = i & 15;
            const __half* src = (seg < 8) ? (w1b + (size_t)(k0 + k) * II + seg * 8)
                                          : (w3b + (size_t)(k0 + k) * II + (seg - 8) * 8);
            int dc = (seg < 8) ? seg * 8 : 64 + (seg - 8) * 8;
            cpa16(bu_ + (uint32_t)(k * BPITCH + dc) * 2, src);
        }
        cpa_commit();
    };

    const int NC = HH / KC; // 12
    fill(0, 0);
    fill(1, 1);

    float accG[4][2][4] = {}, accU[4][2][4] = {};
    int l15 = lane & 15;
    int lhi = (lane & 16) ? 8 : 0;

    for (int c = 0; c < NC; c++) {
        if (c + 1 < NC) cpa_wait<1>(); else cpa_wait<0>();
        __syncthreads();
        if (c + 2 < NC) fill((c + 2) % 3, c + 2);

        uint32_t au = s2u(Ash + (c % 3) * ABUF);
        uint32_t bu_ = s2u(Bsh + (c % 3) * BBUF);
#pragma unroll
        for (int ks = 0; ks < KC / 16; ks++) {
            uint32_t af[4][4];
#pragma unroll
            for (int mf = 0; mf < 4; mf++) {
                int row = warpM * 64 + mf * 16 + l15;
                int col = ks * 16 + lhi;
                ldsm4(af[mf], au + (uint32_t)(row * APITCH + col) * 2);
            }
            int k = ks * 16 + l15;
            int nG = warpN * 16 + lhi;
            uint32_t bg[4], bu2[4];
            ldsm4t(bg,  bu_ + (uint32_t)(k * BPITCH + nG) * 2);
            ldsm4t(bu2, bu_ + (uint32_t)(k * BPITCH + 64 + nG) * 2);
#pragma unroll
            for (int mf = 0; mf < 4; mf++) {
                mma16(accG[mf][0], af[mf], bg);
                mma16(accG[mf][1], af[mf], bg + 2);
                mma16(accU[mf][0], af[mf], bu2);
                mma16(accU[mf][1], af[mf], bu2 + 2);
            }
        }
    }

    // epilogue: SwiGLU, write hbuf as fp16
#pragma unroll
    for (int mf = 0; mf < 4; mf++) {
        int rbase = warpM * 64 + mf * 16 + (lane >> 2);
#pragma unroll
        for (int nf = 0; nf < 2; nf++) {
            int col = bx * 64 + warpN * 16 + nf * 8 + 2 * (lane & 3);
#pragma unroll
            for (int h = 0; h < 2; h++) {
                int r = rbase + h * 8;
                if (r < valid) {
                    float g0 = accG[mf][nf][h * 2 + 0], g1 = accG[mf][nf][h * 2 + 1];
                    float u0 = accU[mf][nf][h * 2 + 0], u1 = accU[mf][nf][h * 2 + 1];
                    __half2 hv = __floats2half2_rn(g0 / (1.0f + expf(-g0)) * u0,
                                                   g1 / (1.0f + expf(-g1)) * u1);
                    *(__half2*)&g_hbufh[((size_t)e * SLOTS + slot0 + r) * II + col] = hv;
                }
            }
        }
    }
}

// ================ GEMM2: fp16 mma + ldmatrix, N=64 tiles, fused combine ====
// CTA: M=128 slots x N=64 H-cols. 256 threads. warp: 64 x 16.
#define BPITCH2 72              // halves per B k-row (64 data + 8 pad) = 144B
#define BBUF2 (KC*BPITCH2)      // halves
#define G2_SMEM ((3*ABUF + 3*BBUF2) * 2 + 128*4 + 128*4)
__global__ void __launch_bounds__(256, 2) gemm2_mma(float* __restrict__ out) {
    extern __shared__ __half sh[];
    __half* Ash = sh;
    __half* Bsh = sh + 3 * ABUF;
    int* tok2 = (int*)(Bsh + 3 * BBUF2);
    float* wt2 = (float*)(tok2 + 128);

    int e = blockIdx.z, by = blockIdx.y, bx = blockIdx.x; // bx 0..11
    int kslot = (by >= 6) ? 1 : 0;
    int cnt = g_cnt[kslot * EE + e];
    int tile0 = (by - kslot * 6) * 128;
    if (tile0 >= cnt) return;
    int valid = min(128, cnt - tile0);
    int slot0 = by * 128;
    int tid = threadIdx.x;
    int lane = tid & 31, w = tid >> 5;
    int warpM = w >> 2, warpN = w & 3;

    if (tid < 128) {
        bool v = tid < valid;
        tok2[tid] = v ? g_list[e * SLOTS + slot0 + tid] : 0;
        wt2[tid]  = v ? g_wslot[e * SLOTS + slot0 + tid] : 0.0f;
    }
    __syncthreads();

    const __half* Ab = g_hbufh + ((size_t)e * SLOTS + slot0) * II;
    const __half* Bb = g_w2h + (size_t)e * II * HH + bx * 64;

    auto fill = [&](int buf, int c) {
        uint32_t au = s2u(Ash + buf * ABUF);
        uint32_t bu_ = s2u(Bsh + buf * BBUF2);
        int k0 = c * KC;
#pragma unroll
        for (int i = tid; i < 1024; i += 256) {
            int row = i >> 3, seg = i & 7;
            cpa16(au + (uint32_t)(row * APITCH + seg * 8) * 2,
                  Ab + (size_t)row * II + k0 + seg * 8);
        }
#pragma unroll
        for (int i = tid; i < 512; i += 256) {   // B: 64 k-rows x 64 halves
            int k = i >> 3, seg = i & 7;
            cpa16(bu_ + (uint32_t)(k * BPITCH2 + seg * 8) * 2,
                  Bb + (size_t)(k0 + k) * HH + seg * 8);
        }
        cpa_commit();
    };

    const int NC = II / KC; // 24
    fill(0, 0);
    fill(1, 1);

    float acc[4][2][4] = {};
    int l15 = lane & 15;
    int lhi = (lane & 16) ? 8 : 0;

    for (int c = 0; c < NC; c++) {
        if (c + 1 < NC) cpa_wait<1>(); else cpa_wait<0>();
        __syncthreads();
        if (c + 2 < NC) fill((c + 2) % 3, c + 2);

        uint32_t au = s2u(Ash + (c % 3) * ABUF);
        uint32_t bu_ = s2u(Bsh + (c % 3) * BBUF2);
#pragma unroll
        for (int ks = 0; ks < KC / 16; ks++) {
            uint32_t af[4][4];
#pragma unroll
            for (int mf = 0; mf < 4; mf++) {
                int row = warpM * 64 + mf * 16 + l15;
                int col = ks * 16 + lhi;
                ldsm4(af[mf], au + (uint32_t)(row * APITCH + col) * 2);
            }
            int k = ks * 16 + l15;
            int nB = warpN * 16 + lhi;
            uint32_t bf[4];
            ldsm4t(bf, bu_ + (uint32_t)(k * BPITCH2 + nB) * 2);
#pragma unroll
            for (int mf = 0; mf < 4; mf++) {
                mma16(acc[mf][0], af[mf], bf);
                mma16(acc[mf][1], af[mf], bf + 2);
            }
        }
    }

    // fused combine: out[token] += w * acc
#pragma unroll
    for (int mf = 0; mf < 4; mf++) {
        int rbase = warpM * 64 + mf * 16 + (lane >> 2);
#pragma unroll
        for (int nf = 0; nf < 2; nf++) {
            int col = bx * 64 + warpN * 16 + nf * 8 + 2 * (lane & 3);
#pragma unroll
            for (int h = 0; h < 2; h++) {
                int r = rbase + h * 8;
                if (r < valid) {
                    float wv = wt2[r];
                    float* op = out + (size_t)tok2[r] * HH + col;
                    atomicAdd(op,     wv * acc[mf][nf][h * 2 + 0]);
                    atomicAdd(op + 1, wv * acc[mf][nf][h * 2 + 1]);
                }
            }
        }
    }
}

// ---------------- aux: importance reduction + scalar ----------------
__global__ void aux_kernel(float* __restrict__ out, int out_size) {
    __shared__ float simp[EE];
    int tid = threadIdx.x, lane = tid & 31, w = tid >> 5;   // 256 thr, 8 warps
    float s = 0.0f;
    for (int t = lane; t < TT; t += 32) s += g_probs[t * EE + w];
#pragma unroll
    for (int o = 16; o; o >>= 1) s += __shfl_xor_sync(0xffffffffu, s, o);
    if (lane == 0) simp[w] = s;
    __syncthreads();
    if (tid == 0 && out_size >= TT * HH + 1) {
        float a = 0.0f;
        int drop = 0;
        for (int e = 0; e < EE; e++) {
            int kept = g_cnt[0 * EE + e] + g_cnt[1 * EE + e];
            drop += g_drop[0 * EE + e] + g_drop[1 * EE + e];
            float usage = (float)kept / (float)(TT * KK);
            float imp = simp[e] / (float)TT;
            a += usage * imp;
        }
        a *= (float)EE;
        if (drop > 0) a += (float)drop / (float)TT * 0.1f;
        a = fminf(a, 1.0f) * 0.001f;
        out[TT * HH] = a;
    }
}

// ---------------- launch ----------------
extern "C" void kernel_launch(void* const* d_in, const int* in_sizes, int n_in,
                              void* d_out, int out_size) {
    const float* x      = (const float*)d_in[0];
    const float* w_gate = (const float*)d_in[1];
    const float* w1     = (const float*)d_in[2];
    const float* w3     = (const float*)d_in[3];
    const float* w2     = (const float*)d_in[4];
    float* out = (float*)d_out;

    cudaFuncSetAttribute(gemm1_mma, cudaFuncAttributeMaxDynamicSharedMemorySize, G1_SMEM);
    cudaFuncSetAttribute(gemm2_mma, cudaFuncAttributeMaxDynamicSharedMemorySize, G2_SMEM);

    __half* w1h_p; cudaGetSymbolAddress((void**)&w1h_p, g_w1h);
    __half* w3h_p; cudaGetSymbolAddress((void**)&w3h_p, g_w3h);
    __half* w2h_p; cudaGetSymbolAddress((void**)&w2h_p, g_w2h);

    const int NW8 = (EE * HH * II) / 8;   // 1179648

    int n4 = out_size / 4;
    zero_out_kernel<<<(n4 + 255) / 256, 256>>>((float4*)out, n4, out, out_size);
    cvth3_kernel<<<dim3((NW8 + 255) / 256, 3), 256>>>(
        (const float4*)w1, (const float4*)w3, (const float4*)w2,
        (uint4*)w1h_p, (uint4*)w3h_p, (uint4*)w2h_p, NW8);
    routing_kernel<<<TT / 16, 512>>>(x, w_gate);
    scan_kernel<<<1, 512>>>();
    gemm1_mma<<<dim3(II / 64, SLOTS / 128, EE), 256, G1_SMEM>>>();
    gemm2_mma<<<dim3(HH / 64, SLOTS / 128, EE), 256, G2_SMEM>>>(out);
    aux_kernel<<<1, 256>>>(out, out_size);
}

// round 17
// speedup vs baseline: 1.0526x; 1.0526x over previous
#include <cuda_runtime.h>
#include <cuda_bf16.h>
#include <cuda_fp16.h>
#include <stdint.h>
#include <math.h>

// Problem constants
#define TT 2048      // tokens (B*S)
#define HH 768       // hidden
#define II 1536      // intermediate
#define EE 8         // experts
#define KK 2         // top-k
#define CAP 768      // capacity
#define SLOTS (KK*CAP)   // 1536 slot rows per expert

// ---------------- scratch (device globals; allocation-free) ----------------
__device__ float g_probs[TT * EE];                // full softmax probs (64KB)
__device__ int   g_topk_idx[TT * KK];
__device__ float g_topk_w[TT * KK];
__device__ int   g_slot[TT * KK];
__device__ int   g_list[EE * SLOTS];
__device__ float g_wslot[EE * SLOTS];             // combine weight per (e,slot)
__device__ int   g_cnt[KK * EE];
__device__ int   g_drop[KK * EE];
__device__ __half g_xh[TT * HH];                  // x as fp16 (3MB)
__device__ __half g_w1h[EE * HH * II];            // w1 fp16 (~19MB)
__device__ __half g_w3h[EE * HH * II];            // w3 fp16 (~19MB)
__device__ __half g_w2h[EE * II * HH];            // w2 fp16 (~19MB)
__device__ __half g_hbufh[EE * SLOTS * II];       // SwiGLU intermediate fp16 (~38MB)

// ---------------- PTX helpers ----------------
__device__ __forceinline__ uint32_t s2u(const void* p) {
    uint32_t a;
    asm("{ .reg .u64 t; cvta.to.shared.u64 t, %1; cvt.u32.u64 %0, t; }" : "=r"(a) : "l"(p));
    return a;
}
__device__ __forceinline__ void cpa16(uint32_t dst, const void* src) {
    asm volatile("cp.async.cg.shared.global [%0], [%1], 16;" :: "r"(dst), "l"(src));
}
__device__ __forceinline__ void cpa_commit() { asm volatile("cp.async.commit_group;" ::: "memory"); }
template<int N> __device__ __forceinline__ void cpa_wait() {
    asm volatile("cp.async.wait_group %0;" :: "n"(N) : "memory");
}
__device__ __forceinline__ void ldsm4(uint32_t* r, uint32_t addr) {
    asm volatile("ldmatrix.sync.aligned.m8n8.x4.shared.b16 {%0,%1,%2,%3}, [%4];"
        : "=r"(r[0]), "=r"(r[1]), "=r"(r[2]), "=r"(r[3]) : "r"(addr));
}
__device__ __forceinline__ void ldsm4t(uint32_t* r, uint32_t addr) {
    asm volatile("ldmatrix.sync.aligned.m8n8.x4.trans.shared.b16 {%0,%1,%2,%3}, [%4];"
        : "=r"(r[0]), "=r"(r[1]), "=r"(r[2]), "=r"(r[3]) : "r"(addr));
}
__device__ __forceinline__ void mma16(float* d, const uint32_t* a, const uint32_t* b) {
    asm volatile(
        "mma.sync.aligned.m16n8k16.row.col.f32.f16.f16.f32 "
        "{%0,%1,%2,%3}, {%4,%5,%6,%7}, {%8,%9}, {%0,%1,%2,%3};"
        : "+f"(d[0]), "+f"(d[1]), "+f"(d[2]), "+f"(d[3])
        : "r"(a[0]), "r"(a[1]), "r"(a[2]), "r"(a[3]), "r"(b[0]), "r"(b[1]));
}

// ---------------- fp16 pre-convert: 8 floats/thread, uint4 store ----------
__global__ void cvth3_kernel(const float4* __restrict__ w1,
                             const float4* __restrict__ w3,
                             const float4* __restrict__ w2,
                             uint4* __restrict__ d1,
                             uint4* __restrict__ d3,
                             uint4* __restrict__ d2, int n8) {
    int i = blockIdx.x * blockDim.x + threadIdx.x;
    if (i >= n8) return;
    const float4* src = (blockIdx.y == 0) ? w1 : (blockIdx.y == 1) ? w3 : w2;
    uint4* dst = (blockIdx.y == 0) ? d1 : (blockIdx.y == 1) ? d3 : d2;
    float4 v0 = src[2 * i];
    float4 v1 = src[2 * i + 1];
    __half2 h0 = __floats2half2_rn(v0.x, v0.y);
    __half2 h1 = __floats2half2_rn(v0.z, v0.w);
    __half2 h2 = __floats2half2_rn(v1.x, v1.y);
    __half2 h3 = __floats2half2_rn(v1.z, v1.w);
    uint4 o;
    o.x = *(uint32_t*)&h0; o.y = *(uint32_t*)&h1;
    o.z = *(uint32_t*)&h2; o.w = *(uint32_t*)&h3;
    dst[i] = o;
}

// ---------------- zero out (float4) ----------------
__global__ void zero_out_kernel(float4* __restrict__ out4, int n4, float* out, int n) {
    int i = blockIdx.x * blockDim.x + threadIdx.x;
    if (i < n4) out4[i] = make_float4(0.f, 0.f, 0.f, 0.f);
    if (i == 0) for (int j = n4 * 4; j < n; j++) out[j] = 0.0f;
}

// ---------------- routing: warp-per-token, wg staged in SMEM ---------------
__global__ void __launch_bounds__(512) routing_kernel(const float* __restrict__ x,
                                                      const float* __restrict__ wg) {
    __shared__ float swgT[EE][HH + 8];
    int tid = threadIdx.x;
    for (int i = tid; i < HH * EE; i += 512) {
        int j = i >> 3, e = i & 7;
        swgT[e][j] = wg[i];
    }
    __syncthreads();

    int lane = tid & 31, w = tid >> 5;
    int t = blockIdx.x * 16 + w;
    const float* xr = x + (size_t)t * HH;
    float acc[EE] = {};
#pragma unroll
    for (int i = 0; i < HH / 128; i++) {            // 6 iterations
        int j = i * 128 + lane * 4;
        float4 xv = *(const float4*)(xr + j);
        __half2 hx0 = __floats2half2_rn(xv.x, xv.y);
        __half2 hx1 = __floats2half2_rn(xv.z, xv.w);
        *(__half2*)&g_xh[(size_t)t * HH + j]     = hx0;
        *(__half2*)&g_xh[(size_t)t * HH + j + 2] = hx1;
#pragma unroll
        for (int e = 0; e < EE; e++) {
            float4 wv = *(const float4*)&swgT[e][j];
            acc[e] += xv.x * wv.x + xv.y * wv.y + xv.z * wv.z + xv.w * wv.w;
        }
    }
#pragma unroll
    for (int o = 16; o; o >>= 1)
#pragma unroll
        for (int e = 0; e < EE; e++) acc[e] += __shfl_xor_sync(0xffffffffu, acc[e], o);

    if (lane == 0) {
        float mx = acc[0];
        for (int e = 1; e < EE; e++) mx = fmaxf(mx, acc[e]);
        float p[EE], s = 0.0f;
        for (int e = 0; e < EE; e++) { p[e] = expf(acc[e] - mx); s += p[e]; }
        for (int e = 0; e < EE; e++) p[e] /= s;
        for (int e = 0; e < EE; e++) g_probs[t * EE + e] = p[e];
        int e0 = 0;
        for (int e = 1; e < EE; e++) if (p[e] > p[e0]) e0 = e;
        int e1 = -1;
        for (int e = 0; e < EE; e++) {
            if (e == e0) continue;
            if (e1 < 0 || p[e] > p[e1]) e1 = e;
        }
        float ps = p[e0] + p[e1] + 1e-8f;
        float w0 = fminf(fmaxf(p[e0] / ps, 1e-8f), 10.0f);
        float w1 = fminf(fmaxf(p[e1] / ps, 1e-8f), 10.0f);
        g_topk_idx[t * 2 + 0] = e0;
        g_topk_idx[t * 2 + 1] = e1;
        g_topk_w[t * 2 + 0] = w0;
        g_topk_w[t * 2 + 1] = w1;
    }
}

// ---------------- scan: SMEM-staged, one warp per (k,e) --------------------
// Stage all topk_idx in SMEM (parallel, one latency step), then each warp
// ballots its (k,e) pair over SMEM (29-cyc LDS, no serial DRAM chain).
__global__ void scan_kernel() {       // 1 block, 512 threads = 16 warps
    __shared__ int sidx[TT * KK];     // 16 KB
    int tid = threadIdx.x;
    for (int i = tid; i < TT * KK / 4; i += 512)
        *(int4*)&sidx[i * 4] = *(const int4*)&g_topk_idx[i * 4];
    __syncthreads();

    int w = tid >> 5, lane = tid & 31;
    int k = w >> 3, e = w & 7;
    int cnt = 0;
    for (int t0 = 0; t0 < TT; t0 += 32) {
        int t = t0 + lane;
        bool m = (sidx[t * 2 + k] == e);
        unsigned mask = __ballot_sync(0xffffffffu, m);
        if (m) {
            int rank = cnt + __popc(mask & ((1u << lane) - 1)) + 1;
            bool kept = (rank <= CAP);
            int slot = kept ? (k * CAP + rank - 1) : -1;
            g_slot[t * 2 + k] = slot;
            if (kept) {
                g_list[e * SLOTS + slot] = t;
                g_wslot[e * SLOTS + slot] = g_topk_w[t * 2 + k];
            }
        }
        cnt += __popc(mask);
    }
    if (lane == 0) {
        int c = min(cnt, CAP);
        g_cnt[k * EE + e] = c;
        g_drop[k * EE + e] = cnt - c;
    }
}

// ================ GEMM1: fp16 mma + ldmatrix, KC=64, 3-stage, 2 CTAs/SM ====
// CTA: M=128 slots x N=128 (64 w1-cols + 64 w3-cols). 256 threads, 8 warps.
#define KC 64                   // K elements per chunk
#define APITCH 72               // halves per A row (64 data + 8 pad) = 144B
#define BPITCH 136              // halves per B k-row (128 data + 8 pad) = 272B
#define ABUF (128*APITCH)       // halves
#define BBUF (KC*BPITCH)        // halves
#define G1_SMEM ((3*ABUF + 3*BBUF) * 2 + 512)
__global__ void __launch_bounds__(256, 2) gemm1_mma() {
    extern __shared__ __half sh[];
    __half* Ash = sh;                 // 3 x ABUF
    __half* Bsh = sh + 3 * ABUF;      // 3 x BBUF
    int* stok = (int*)(Bsh + 3 * BBUF);

    int e = blockIdx.z, by = blockIdx.y, bx = blockIdx.x; // bx 0..23
    int kslot = (by >= 6) ? 1 : 0;
    int cnt = g_cnt[kslot * EE + e];
    int tile0 = (by - kslot * 6) * 128;
    if (tile0 >= cnt) return;
    int valid = min(128, cnt - tile0);
    int slot0 = by * 128;
    int tid = threadIdx.x;
    int lane = tid & 31, w = tid >> 5;
    int warpM = w >> 2, warpN = w & 3;

    if (tid < 128)
        stok[tid] = (tid < valid) ? g_list[e * SLOTS + slot0 + tid]
                                  : g_list[e * SLOTS + slot0];
    __syncthreads();

    const __half* w1b = g_w1h + (size_t)e * HH * II + bx * 64;
    const __half* w3b = g_w3h + (size_t)e * HH * II + bx * 64;

    auto fill = [&](int buf, int c) {
        uint32_t au = s2u(Ash + buf * ABUF);
        uint32_t bu_ = s2u(Bsh + buf * BBUF);
        int k0 = c * KC;
#pragma unroll
        for (int i = tid; i < 1024; i += 256) {   // A: 128 rows x 64 halves
            int row = i >> 3, seg = i & 7;
            cpa16(au + (uint32_t)(row * APITCH + seg * 8) * 2,
                  g_xh + (size_t)stok[row] * HH + k0 + seg * 8);
        }
#pragma unroll
        for (int i = tid; i < 1024; i += 256) {   // B: 64 k-rows x (64 G + 64 U)
            int k = i >> 4, seg = i & 15;
            const __half* src = (seg < 8) ? (w1b + (size_t)(k0 + k) * II + seg * 8)
                                          : (w3b + (size_t)(k0 + k) * II + (seg - 8) * 8);
            int dc = (seg < 8) ? seg * 8 : 64 + (seg - 8) * 8;
            cpa16(bu_ + (uint32_t)(k * BPITCH + dc) * 2, src);
        }
        cpa_commit();
    };

    const int NC = HH / KC; // 12
    fill(0, 0);
    fill(1, 1);

    float accG[4][2][4] = {}, accU[4][2][4] = {};
    int l15 = lane & 15;
    int lhi = (lane & 16) ? 8 : 0;

    for (int c = 0; c < NC; c++) {
        if (c + 1 < NC) cpa_wait<1>(); else cpa_wait<0>();
        __syncthreads();
        if (c + 2 < NC) fill((c + 2) % 3, c + 2);

        uint32_t au = s2u(Ash + (c % 3) * ABUF);
        uint32_t bu_ = s2u(Bsh + (c % 3) * BBUF);
#pragma unroll
        for (int ks = 0; ks < KC / 16; ks++) {
            uint32_t af[4][4];
#pragma unroll
            for (int mf = 0; mf < 4; mf++) {
                int row = warpM * 64 + mf * 16 + l15;
                int col = ks * 16 + lhi;
                ldsm4(af[mf], au + (uint32_t)(row * APITCH + col) * 2);
            }
            int k = ks * 16 + l15;
            int nG = warpN * 16 + lhi;
            uint32_t bg[4], bu2[4];
            ldsm4t(bg,  bu_ + (uint32_t)(k * BPITCH + nG) * 2);
            ldsm4t(bu2, bu_ + (uint32_t)(k * BPITCH + 64 + nG) * 2);
#pragma unroll
            for (int mf = 0; mf < 4; mf++) {
                mma16(accG[mf][0], af[mf], bg);
                mma16(accG[mf][1], af[mf], bg + 2);
                mma16(accU[mf][0], af[mf], bu2);
                mma16(accU[mf][1], af[mf], bu2 + 2);
            }
        }
    }

    // epilogue: SwiGLU, write hbuf as fp16
#pragma unroll
    for (int mf = 0; mf < 4; mf++) {
        int rbase = warpM * 64 + mf * 16 + (lane >> 2);
#pragma unroll
        for (int nf = 0; nf < 2; nf++) {
            int col = bx * 64 + warpN * 16 + nf * 8 + 2 * (lane & 3);
#pragma unroll
            for (int h = 0; h < 2; h++) {
                int r = rbase + h * 8;
                if (r < valid) {
                    float g0 = accG[mf][nf][h * 2 + 0], g1 = accG[mf][nf][h * 2 + 1];
                    float u0 = accU[mf][nf][h * 2 + 0], u1 = accU[mf][nf][h * 2 + 1];
                    __half2 hv = __floats2half2_rn(g0 / (1.0f + expf(-g0)) * u0,
                                                   g1 / (1.0f + expf(-g1)) * u1);
                    *(__half2*)&g_hbufh[((size_t)e * SLOTS + slot0 + r) * II + col] = hv;
                }
            }
        }
    }
}

// ================ GEMM2: fp16 mma + ldmatrix, N=64 tiles, fused combine ====
// CTA: M=128 slots x N=64 H-cols. 256 threads. warp: 64 x 16.
#define BPITCH2 72              // halves per B k-row (64 data + 8 pad) = 144B
#define BBUF2 (KC*BPITCH2)      // halves
#define G2_SMEM ((3*ABUF + 3*BBUF2) * 2 + 128*4 + 128*4)
__global__ void __launch_bounds__(256, 2) gemm2_mma(float* __restrict__ out) {
    extern __shared__ __half sh[];
    __half* Ash = sh;
    __half* Bsh = sh + 3 * ABUF;
    int* tok2 = (int*)(Bsh + 3 * BBUF2);
    float* wt2 = (float*)(tok2 + 128);

    int e = blockIdx.z, by = blockIdx.y, bx = blockIdx.x; // bx 0..11
    int kslot = (by >= 6) ? 1 : 0;
    int cnt = g_cnt[kslot * EE + e];
    int tile0 = (by - kslot * 6) * 128;
    if (tile0 >= cnt) return;
    int valid = min(128, cnt - tile0);
    int slot0 = by * 128;
    int tid = threadIdx.x;
    int lane = tid & 31, w = tid >> 5;
    int warpM = w >> 2, warpN = w & 3;

    if (tid < 128) {
        bool v = tid < valid;
        tok2[tid] = v ? g_list[e * SLOTS + slot0 + tid] : 0;
        wt2[tid]  = v ? g_wslot[e * SLOTS + slot0 + tid] : 0.0f;
    }
    __syncthreads();

    const __half* Ab = g_hbufh + ((size_t)e * SLOTS + slot0) * II;
    const __half* Bb = g_w2h + (size_t)e * II * HH + bx * 64;

    auto fill = [&](int buf, int c) {
        uint32_t au = s2u(Ash + buf * ABUF);
        uint32_t bu_ = s2u(Bsh + buf * BBUF2);
        int k0 = c * KC;
#pragma unroll
        for (int i = tid; i < 1024; i += 256) {
            int row = i >> 3, seg = i & 7;
            cpa16(au + (uint32_t)(row * APITCH + seg * 8) * 2,
                  Ab + (size_t)row * II + k0 + seg * 8);
        }
#pragma unroll
        for (int i = tid; i < 512; i += 256) {   // B: 64 k-rows x 64 halves
            int k = i >> 3, seg = i & 7;
            cpa16(bu_ + (uint32_t)(k * BPITCH2 + seg * 8) * 2,
                  Bb + (size_t)(k0 + k) * HH + seg * 8);
        }
        cpa_commit();
    };

    const int NC = II / KC; // 24
    fill(0, 0);
    fill(1, 1);

    float acc[4][2][4] = {};
    int l15 = lane & 15;
    int lhi = (lane & 16) ? 8 : 0;

    for (int c = 0; c < NC; c++) {
        if (c + 1 < NC) cpa_wait<1>(); else cpa_wait<0>();
        __syncthreads();
        if (c + 2 < NC) fill((c + 2) % 3, c + 2);

        uint32_t au = s2u(Ash + (c % 3) * ABUF);
        uint32_t bu_ = s2u(Bsh + (c % 3) * BBUF2);
#pragma unroll
        for (int ks = 0; ks < KC / 16; ks++) {
            uint32_t af[4][4];
#pragma unroll
            for (int mf = 0; mf < 4; mf++) {
                int row = warpM * 64 + mf * 16 + l15;
                int col = ks * 16 + lhi;
                ldsm4(af[mf], au + (uint32_t)(row * APITCH + col) * 2);
            }
            int k = ks * 16 + l15;
            int nB = warpN * 16 + lhi;
            uint32_t bf[4];
            ldsm4t(bf, bu_ + (uint32_t)(k * BPITCH2 + nB) * 2);
#pragma unroll
            for (int mf = 0; mf < 4; mf++) {
                mma16(acc[mf][0], af[mf], bf);
                mma16(acc[mf][1], af[mf], bf + 2);
            }
        }
    }

    // fused combine: out[token] += w * acc
#pragma unroll
    for (int mf = 0; mf < 4; mf++) {
        int rbase = warpM * 64 + mf * 16 + (lane >> 2);
#pragma unroll
        for (int nf = 0; nf < 2; nf++) {
            int col = bx * 64 + warpN * 16 + nf * 8 + 2 * (lane & 3);
#pragma unroll
            for (int h = 0; h < 2; h++) {
                int r = rbase + h * 8;
                if (r < valid) {
                    float wv = wt2[r];
                    float* op = out + (size_t)tok2[r] * HH + col;
                    atomicAdd(op,     wv * acc[mf][nf][h * 2 + 0]);
                    atomicAdd(op + 1, wv * acc[mf][nf][h * 2 + 1]);
                }
            }
        }
    }
}

// ---------------- aux: importance reduction + scalar ----------------
__global__ void aux_kernel(float* __restrict__ out, int out_size) {
    __shared__ float simp[EE];
    int tid = threadIdx.x, lane = tid & 31, w = tid >> 5;   // 256 thr, 8 warps
    float s = 0.0f;
    for (int t = lane; t < TT; t += 32) s += g_probs[t * EE + w];
#pragma unroll
    for (int o = 16; o; o >>= 1) s += __shfl_xor_sync(0xffffffffu, s, o);
    if (lane == 0) simp[w] = s;
    __syncthreads();
    if (tid == 0 && out_size >= TT * HH + 1) {
        float a = 0.0f;
        int drop = 0;
        for (int e = 0; e < EE; e++) {
            int kept = g_cnt[0 * EE + e] + g_cnt[1 * EE + e];
            drop += g_drop[0 * EE + e] + g_drop[1 * EE + e];
            float usage = (float)kept / (float)(TT * KK);
            float imp = simp[e] / (float)TT;
            a += usage * imp;
        }
        a *= (float)EE;
        if (drop > 0) a += (float)drop / (float)TT * 0.1f;
        a = fminf(a, 1.0f) * 0.001f;
        out[TT * HH] = a;
    }
}

// ---------------- launch ----------------
extern "C" void kernel_launch(void* const* d_in, const int* in_sizes, int n_in,
                              void* d_out, int out_size) {
    const float* x      = (const float*)d_in[0];
    const float* w_gate = (const float*)d_in[1];
    const float* w1     = (const float*)d_in[2];
    const float* w3     = (const float*)d_in[3];
    const float* w2     = (const float*)d_in[4];
    float* out = (float*)d_out;

    cudaFuncSetAttribute(gemm1_mma, cudaFuncAttributeMaxDynamicSharedMemorySize, G1_SMEM);
    cudaFuncSetAttribute(gemm2_mma, cudaFuncAttributeMaxDynamicSharedMemorySize, G2_SMEM);

    __half* w1h_p; cudaGetSymbolAddress((void**)&w1h_p, g_w1h);
    __half* w3h_p; cudaGetSymbolAddress((void**)&w3h_p, g_w3h);
    __half* w2h_p; cudaGetSymbolAddress((void**)&w2h_p, g_w2h);

    const int NW8 = (EE * HH * II) / 8;   // 1179648

    int n4 = out_size / 4;
    zero_out_kernel<<<(n4 + 255) / 256, 256>>>((float4*)out, n4, out, out_size);
    cvth3_kernel<<<dim3((NW8 + 255) / 256, 3), 256>>>(
        (const float4*)w1, (const float4*)w3, (const float4*)w2,
        (uint4*)w1h_p, (uint4*)w3h_p, (uint4*)w2h_p, NW8);
    routing_kernel<<<TT / 16, 512>>>(x, w_gate);
    scan_kernel<<<1, 512>>>();
    gemm1_mma<<<dim3(II / 64, SLOTS / 128, EE), 256, G1_SMEM>>>();
    gemm2_mma<<<dim3(HH / 64, SLOTS / 128, EE), 256, G2_SMEM>>>(out);
    aux_kernel<<<1, 256>>>(out, out_size);
}